// round 4
// baseline (speedup 1.0000x reference)
#include <cuda_runtime.h>
#include <cuda_bf16.h>
#include <cstdint>

// Problem constants: S=2048, B=1, D=1280, H=16, HD=80, NSEQ=8
#define S_TOT   2048
#define D_MODEL 1280
#define THREE_D 3840
#define NHEAD   16
#define HDIM    80

// Device scratch (no allocs allowed)
__device__ float g_qkv[S_TOT * THREE_D];              // qkv output, 31.5MB
__device__ float g_xt[S_TOT * D_MODEL];               // tf32-rounded X
__device__ float g_wt[THREE_D * D_MODEL];             // tf32-rounded W

// ============================ helpers ==================================
__device__ __forceinline__ uint32_t smem_u32(const void* p) {
    uint32_t a;
    asm("{ .reg .u64 t; cvta.to.shared.u64 t, %1; cvt.u32.u64 %0, t; }"
        : "=r"(a) : "l"(p));
    return a;
}
__device__ __forceinline__ uint32_t f2tf32(float f) {
    uint32_t u;
    asm("cvt.rna.tf32.f32 %0, %1;" : "=r"(u) : "f"(f));
    return u;
}
__device__ __forceinline__ void split2(float x, uint32_t& hi, uint32_t& lo) {
    hi = f2tf32(x);
    lo = f2tf32(x - __uint_as_float(hi));
}
__device__ __forceinline__ void cp16(uint32_t dst, const void* src) {
    asm volatile("cp.async.ca.shared.global [%0], [%1], 16;"
                 :: "r"(dst), "l"(src));
}
#define CP_COMMIT() asm volatile("cp.async.commit_group;" ::: "memory")
#define CP_WAIT1()  asm volatile("cp.async.wait_group 1;" ::: "memory")

__device__ __forceinline__ void mma_tf32(float* d, const uint32_t* a,
                                         const uint32_t* b) {
    asm volatile(
        "mma.sync.aligned.m16n8k8.row.col.f32.tf32.tf32.f32 "
        "{%0,%1,%2,%3}, {%4,%5,%6,%7}, {%8,%9}, {%0,%1,%2,%3};"
        : "+f"(d[0]), "+f"(d[1]), "+f"(d[2]), "+f"(d[3])
        : "r"(a[0]), "r"(a[1]), "r"(a[2]), "r"(a[3]), "r"(b[0]), "r"(b[1]));
}

// ---------------------------------------------------------------------------
// Kernel 0: fp32 -> tf32 (round-to-nearest) pre-conversion
// ---------------------------------------------------------------------------
__global__ __launch_bounds__(256) void cvt_tf32_kernel(
    const float4* __restrict__ src, float4* __restrict__ dst, int n4)
{
    int i = blockIdx.x * 256 + threadIdx.x;
    if (i < n4) {
        float4 v = src[i];
        uint4 u = make_uint4(f2tf32(v.x), f2tf32(v.y), f2tf32(v.z), f2tf32(v.w));
        *(uint4*)&dst[i] = u;
    }
}

// ---------------------------------------------------------------------------
// Kernel 1: TF32 mma.sync QKV GEMM (unchanged from R3 — passed at ~120us).
// ---------------------------------------------------------------------------
#define BK      32
#define KCHUNK  (D_MODEL / BK)          // 40
#define ASTRIDE 36
#define ASZF    (128 * ASTRIDE)
#define BSZF    (256 * ASTRIDE)
#define STAGEF  (ASZF + BSZF)
#define NSTAGE  3
#define GEMM_SMEM_BYTES (NSTAGE * STAGEF * 4)

__global__ __launch_bounds__(256) void qkv_gemm_mma(
    const float* __restrict__ bias)
{
    extern __shared__ float smf[];
    const uint32_t sb = smem_u32(smf);
    const int tid = threadIdx.x;
    const int wid = tid >> 5, lane = tid & 31;
    const int wm = wid & 1, wn = wid >> 1;
    const int r  = lane >> 2, cq = lane & 3;
    const int m0 = blockIdx.y * 128;
    const int n0 = blockIdx.x * 256;

    const float* Xb = g_xt + (size_t)m0 * D_MODEL;
    const float* Wb = g_wt + (size_t)n0 * D_MODEL;

    auto issue = [&](int c, int s) {
        const int kk = c * BK;
        const uint32_t ab = sb + (uint32_t)(s * STAGEF) * 4u;
        const uint32_t bb = ab + (uint32_t)ASZF * 4u;
#pragma unroll
        for (int j = 0; j < 4; j++) {
            const int idx = tid + 256 * j;
            const int row = idx >> 3, kc = (idx & 7) << 2;
            cp16(ab + (uint32_t)(row * ASTRIDE + kc) * 4u,
                 Xb + (size_t)row * D_MODEL + kk + kc);
        }
#pragma unroll
        for (int j = 0; j < 8; j++) {
            const int idx = tid + 256 * j;
            const int row = idx >> 3, kc = (idx & 7) << 2;
            cp16(bb + (uint32_t)(row * ASTRIDE + kc) * 4u,
                 Wb + (size_t)row * D_MODEL + kk + kc);
        }
    };

    float acc[4][8][4];
#pragma unroll
    for (int mi = 0; mi < 4; mi++)
#pragma unroll
        for (int ni = 0; ni < 8; ni++)
#pragma unroll
            for (int q = 0; q < 4; q++) acc[mi][ni][q] = 0.0f;

    issue(0, 0); CP_COMMIT();
    issue(1, 1); CP_COMMIT();

    for (int c = 0; c < KCHUNK; c++) {
        const int s = c % NSTAGE;
        CP_WAIT1();
        __syncthreads();

        if (c + 2 < KCHUNK) issue(c + 2, (c + 2) % NSTAGE);
        CP_COMMIT();

        const uint32_t* Sa = (const uint32_t*)smf + s * STAGEF
                             + (wm * 64 + r) * ASTRIDE + cq;
        const uint32_t* Sb2 = (const uint32_t*)smf + s * STAGEF + ASZF
                              + (wn * 64 + r) * ASTRIDE + cq;
#pragma unroll
        for (int ks = 0; ks < 4; ks++) {
            uint32_t a[4][4], b[8][2];
            const int ko = ks * 8;
#pragma unroll
            for (int mi = 0; mi < 4; mi++) {
                a[mi][0] = Sa[(mi * 16 + 0) * ASTRIDE + ko];
                a[mi][1] = Sa[(mi * 16 + 8) * ASTRIDE + ko];
                a[mi][2] = Sa[(mi * 16 + 0) * ASTRIDE + ko + 4];
                a[mi][3] = Sa[(mi * 16 + 8) * ASTRIDE + ko + 4];
            }
#pragma unroll
            for (int ni = 0; ni < 8; ni++) {
                b[ni][0] = Sb2[ni * 8 * ASTRIDE + ko];
                b[ni][1] = Sb2[ni * 8 * ASTRIDE + ko + 4];
            }
#pragma unroll
            for (int mi = 0; mi < 4; mi++)
#pragma unroll
                for (int ni = 0; ni < 8; ni++)
                    mma_tf32(acc[mi][ni], a[mi], b[ni]);
        }
    }

    float bb[8][2];
#pragma unroll
    for (int ni = 0; ni < 8; ni++) {
        const int ncol = n0 + wn * 64 + ni * 8 + cq * 2;
        bb[ni][0] = bias[ncol];
        bb[ni][1] = bias[ncol + 1];
    }
#pragma unroll
    for (int mi = 0; mi < 4; mi++) {
        const int row0 = m0 + wm * 64 + mi * 16 + r;
#pragma unroll
        for (int ni = 0; ni < 8; ni++) {
            const int ncol = n0 + wn * 64 + ni * 8 + cq * 2;
            float2 v0 = make_float2(acc[mi][ni][0] + bb[ni][0],
                                    acc[mi][ni][1] + bb[ni][1]);
            float2 v1 = make_float2(acc[mi][ni][2] + bb[ni][0],
                                    acc[mi][ni][3] + bb[ni][1]);
            *(float2*)&g_qkv[(size_t)row0 * THREE_D + ncol] = v0;
            *(float2*)&g_qkv[(size_t)(row0 + 8) * THREE_D + ncol] = v1;
        }
    }
}

// ---------------------------------------------------------------------------
// Kernel 2: tensor-core block-diagonal attention (3xTF32 for both GEMMs).
// One CTA per (seg, head). K[256][80] + V^T[80][256] in SMEM; 8 chunks of
// 32 query rows: S=QK^T (mma) -> softmax -> O=PV (mma).
// ---------------------------------------------------------------------------
#define KS_STR 84    // K row stride: frag banks (g*20 + c) all-distinct
#define VT_STR 260   // V^T row stride: frag banks (g*4 + c) all-distinct
#define SB_STR 268   // S row stride: PV A-frag banks (g*12 + c) all-distinct
#define OFF_V  (256 * KS_STR)
#define OFF_S  (OFF_V + 80 * VT_STR)
#define OFF_Q  (OFF_S + 32 * SB_STR)
#define OFF_R  (OFF_Q + 32 * KS_STR)
#define ATTN_SMEM_BYTES ((OFF_R + 32) * 4)   // 214,400 B

#define QSCALE 0.11180339887498949f          // 1/sqrt(80)
#define LOG2E  1.4426950408889634f

__global__ __launch_bounds__(256) void attn_tc(
    const int* __restrict__ cu, float* __restrict__ out)
{
    const int seg = blockIdx.x, h = blockIdx.y;
    const int s0 = cu[seg];
    const int L  = cu[seg + 1] - s0;
    const int tid = threadIdx.x;
    const int wid = tid >> 5, lane = tid & 31;
    const int gq = lane >> 2, cq = lane & 3;   // frag row-group / k-quad

    extern __shared__ float sm[];
    float* Ks = sm;                // [256][KS_STR]
    float* Vt = sm + OFF_V;        // [80][VT_STR]  (V transposed)
    float* Sb = sm + OFF_S;        // [32][SB_STR]
    float* Qs = sm + OFF_Q;        // [32][KS_STR]
    float* rs = sm + OFF_R;        // [32] row sums

    const float* QKV = g_qkv;

    // ---- Load K (row-major, float4) and V^T (transposed, scalar) ----
    for (int idx = tid; idx < 256 * 20; idx += 256) {
        const int t = idx / 20, c = (idx % 20) * 4;
        float4 v = make_float4(0.f, 0.f, 0.f, 0.f);
        if (t < L)
            v = *(const float4*)(QKV + (size_t)(s0 + t) * THREE_D + D_MODEL + h * HDIM + c);
        *(float4*)&Ks[t * KS_STR + c] = v;
    }
    for (int idx = tid; idx < 256 * 80; idx += 256) {
        const int t = idx / 80, d = idx % 80;
        float v = 0.f;
        if (t < L)
            v = QKV[(size_t)(s0 + t) * THREE_D + 2 * D_MODEL + h * HDIM + d];
        Vt[d * VT_STR + t] = v;
    }
    __syncthreads();

    const int wm = wid & 1, wn = wid >> 1;     // scores: 2m x 4n warp grid

    for (int ch = 0; ch < 8; ch++) {
        const int r0 = ch * 32;

        // ---- Stage Q chunk (pre-scaled by 1/sqrt(HD)) ----
        for (int idx = tid; idx < 32 * 20; idx += 256) {
            const int row = idx / 20, c = (idx % 20) * 4;
            float4 v = make_float4(0.f, 0.f, 0.f, 0.f);
            if (r0 + row < L)
                v = *(const float4*)(QKV + (size_t)(s0 + r0 + row) * THREE_D + h * HDIM + c);
            v.x *= QSCALE; v.y *= QSCALE; v.z *= QSCALE; v.w *= QSCALE;
            *(float4*)&Qs[row * KS_STR + c] = v;
        }
        __syncthreads();

        // ---- Scores: warp computes m16 (rows wm*16) x n64 (cols wn*64) ----
        {
            float acc[8][4];
#pragma unroll
            for (int nt = 0; nt < 8; nt++)
#pragma unroll
                for (int q = 0; q < 4; q++) acc[nt][q] = 0.f;

#pragma unroll
            for (int k0 = 0; k0 < 80; k0 += 8) {
                const float* qp = Qs + (wm * 16 + gq) * KS_STR + k0 + cq;
                uint32_t ah[4], al[4];
                split2(qp[0],               ah[0], al[0]);
                split2(qp[8 * KS_STR],      ah[1], al[1]);
                split2(qp[4],               ah[2], al[2]);
                split2(qp[8 * KS_STR + 4],  ah[3], al[3]);
#pragma unroll
                for (int nt = 0; nt < 8; nt++) {
                    const float* kp = Ks + (wn * 64 + nt * 8 + gq) * KS_STR + k0 + cq;
                    uint32_t bh[2], bl[2];
                    split2(kp[0], bh[0], bl[0]);
                    split2(kp[4], bh[1], bl[1]);
                    mma_tf32(acc[nt], ah, bh);
                    mma_tf32(acc[nt], al, bh);
                    mma_tf32(acc[nt], ah, bl);
                }
            }
            // store S chunk
#pragma unroll
            for (int nt = 0; nt < 8; nt++) {
                const int col = wn * 64 + nt * 8 + 2 * cq;
                Sb[(wm * 16 + gq) * SB_STR + col]     = acc[nt][0];
                Sb[(wm * 16 + gq) * SB_STR + col + 1] = acc[nt][1];
                Sb[(wm * 16 + gq + 8) * SB_STR + col]     = acc[nt][2];
                Sb[(wm * 16 + gq + 8) * SB_STR + col + 1] = acc[nt][3];
            }
        }
        __syncthreads();

        // ---- Softmax: warp handles 4 rows; lane covers cols lane+32j ----
#pragma unroll
        for (int i = 0; i < 4; i++) {
            const int row = wid * 4 + i;
            float v[8], m = -1e30f;
#pragma unroll
            for (int j = 0; j < 8; j++) {
                const int col = lane + 32 * j;
                v[j] = (col < L) ? Sb[row * SB_STR + col] : -1e30f;
                m = fmaxf(m, v[j]);
            }
#pragma unroll
            for (int off = 16; off; off >>= 1)
                m = fmaxf(m, __shfl_xor_sync(0xffffffffu, m, off));
            float sum = 0.f;
#pragma unroll
            for (int j = 0; j < 8; j++) {
                const float e = exp2f((v[j] - m) * LOG2E);
                Sb[row * SB_STR + lane + 32 * j] = e;
                sum += e;
            }
#pragma unroll
            for (int off = 16; off; off >>= 1)
                sum += __shfl_xor_sync(0xffffffffu, sum, off);
            if (lane == 0) rs[row] = sum;
        }
        __syncthreads();

        // ---- PV: 20 jobs (mi in 0..1, ni in 0..9), warp takes wid, wid+8, wid+16
        for (int j = wid; j < 20; j += 8) {
            const int mi = j / 10, ni = j % 10;
            float acc[4] = {0.f, 0.f, 0.f, 0.f};
#pragma unroll 4
            for (int k0 = 0; k0 < 256; k0 += 8) {
                const float* pp = Sb + (mi * 16 + gq) * SB_STR + k0 + cq;
                uint32_t ah[4], al[4];
                split2(pp[0],               ah[0], al[0]);
                split2(pp[8 * SB_STR],      ah[1], al[1]);
                split2(pp[4],               ah[2], al[2]);
                split2(pp[8 * SB_STR + 4],  ah[3], al[3]);
                const float* vp = Vt + (ni * 8 + gq) * VT_STR + k0 + cq;
                uint32_t bh[2], bl[2];
                split2(vp[0], bh[0], bl[0]);
                split2(vp[4], bh[1], bl[1]);
                mma_tf32(acc, ah, bh);
                mma_tf32(acc, al, bh);
                mma_tf32(acc, ah, bl);
            }
            const int row0 = mi * 16 + gq;
            const int d0   = ni * 8 + 2 * cq;
            const float inv0 = 1.0f / rs[row0];
            const float inv1 = 1.0f / rs[row0 + 8];
            if (r0 + row0 < L) {
                float2 o = make_float2(acc[0] * inv0, acc[1] * inv0);
                *(float2*)&out[(size_t)(s0 + r0 + row0) * (NHEAD * HDIM) + h * HDIM + d0] = o;
            }
            if (r0 + row0 + 8 < L) {
                float2 o = make_float2(acc[2] * inv1, acc[3] * inv1);
                *(float2*)&out[(size_t)(s0 + r0 + row0 + 8) * (NHEAD * HDIM) + h * HDIM + d0] = o;
            }
        }
        __syncthreads();
    }
}

// ---------------------------------------------------------------------------
extern "C" void kernel_launch(void* const* d_in, const int* in_sizes, int n_in,
                              void* d_out, int out_size)
{
    const float* x    = (const float*)d_in[0];   // [2048,1,1280]
    const int*   cu   = (const int*)d_in[1];     // [9]
    const float* Wqkv = (const float*)d_in[2];   // [3840,1280]
    const float* bqkv = (const float*)d_in[3];   // [3840]
    float* out = (float*)d_out;                  // [1,2048,16,80]

    const int nseg = in_sizes[1] - 1;

    float *xt_p, *wt_p;
    cudaGetSymbolAddress((void**)&xt_p, g_xt);
    cudaGetSymbolAddress((void**)&wt_p, g_wt);

    const int n4x = S_TOT * D_MODEL / 4;
    const int n4w = THREE_D * D_MODEL / 4;
    cvt_tf32_kernel<<<(n4x + 255) / 256, 256>>>((const float4*)x, (float4*)xt_p, n4x);
    cvt_tf32_kernel<<<(n4w + 255) / 256, 256>>>((const float4*)Wqkv, (float4*)wt_p, n4w);

    cudaFuncSetAttribute(qkv_gemm_mma,
                         cudaFuncAttributeMaxDynamicSharedMemorySize,
                         GEMM_SMEM_BYTES);
    dim3 ggrid(THREE_D / 256, S_TOT / 128);
    qkv_gemm_mma<<<ggrid, 256, GEMM_SMEM_BYTES>>>(bqkv);

    cudaFuncSetAttribute(attn_tc,
                         cudaFuncAttributeMaxDynamicSharedMemorySize,
                         ATTN_SMEM_BYTES);
    attn_tc<<<dim3(nseg, NHEAD), 256, ATTN_SMEM_BYTES>>>(cu, out);
}